// round 1
// baseline (speedup 1.0000x reference)
#include <cuda_runtime.h>
#include <math.h>

#define BB   4
#define SS   2048
#define HH   1024
#define NHH  16
#define HDD  64
#define MM   (BB*SS)   /* 8192 tokens */

// ---------------- scratch (device globals: allocation-free) ----------------
__device__ float g_q[(size_t)MM*HH];
__device__ float g_k[(size_t)MM*HH];
__device__ float g_v[(size_t)MM*HH];
__device__ float g_g[(size_t)MM*HH];
__device__ float g_ab[(size_t)MM*2*NHH];
__device__ float g_attn[(size_t)MM*HH];
__device__ float g_z[(size_t)MM*HH];

// ---------------------------------------------------------------------------
// SGEMM: C[M,N] = A[M,K] @ B[N,K]^T  (both row-major), tiles 128x128x8,
// 256 threads, 8x8 per thread, double-buffered shared.
// M, N, K all multiples of 128/8 here — no edge guards.
// ---------------------------------------------------------------------------
__global__ __launch_bounds__(256) void sgemm_nt(const float* __restrict__ A,
                                                const float* __restrict__ Bm,
                                                float* __restrict__ C,
                                                int K, int N)
{
    const int tid  = threadIdx.x;
    const int tx   = tid & 15;       // col group 0..15
    const int ty   = tid >> 4;       // row group 0..15
    const int row0 = blockIdx.y * 128;
    const int col0 = blockIdx.x * 128;

    __shared__ float As[2][8][128];
    __shared__ float Bs[2][8][128];

    const int lr = tid >> 1;          // 0..127
    const int lk = (tid & 1) << 2;    // 0 or 4
    const float* Ap = A  + (size_t)(row0 + lr) * K + lk;
    const float* Bp = Bm + (size_t)(col0 + lr) * K + lk;

    float4 a4 = *(const float4*)Ap;
    float4 b4 = *(const float4*)Bp;
    As[0][lk+0][lr]=a4.x; As[0][lk+1][lr]=a4.y; As[0][lk+2][lr]=a4.z; As[0][lk+3][lr]=a4.w;
    Bs[0][lk+0][lr]=b4.x; Bs[0][lk+1][lr]=b4.y; Bs[0][lk+2][lr]=b4.z; Bs[0][lk+3][lr]=b4.w;
    __syncthreads();

    float acc[8][8] = {};
    const int nk = K >> 3;
    int buf = 0;

    for (int kt = 0; kt < nk; ++kt) {
        float4 na, nb;
        const bool have_next = (kt + 1 < nk);
        if (have_next) {
            na = *(const float4*)(Ap + (size_t)(kt+1)*8);
            nb = *(const float4*)(Bp + (size_t)(kt+1)*8);
        }
        #pragma unroll
        for (int kk = 0; kk < 8; ++kk) {
            float af[8], bf[8];
            *(float4*)(af)   = *(const float4*)&As[buf][kk][ty*8];
            *(float4*)(af+4) = *(const float4*)&As[buf][kk][ty*8+4];
            *(float4*)(bf)   = *(const float4*)&Bs[buf][kk][tx*8];
            *(float4*)(bf+4) = *(const float4*)&Bs[buf][kk][tx*8+4];
            #pragma unroll
            for (int i = 0; i < 8; ++i)
                #pragma unroll
                for (int j = 0; j < 8; ++j)
                    acc[i][j] = fmaf(af[i], bf[j], acc[i][j]);
        }
        if (have_next) {
            const int nb2 = buf ^ 1;
            As[nb2][lk+0][lr]=na.x; As[nb2][lk+1][lr]=na.y; As[nb2][lk+2][lr]=na.z; As[nb2][lk+3][lr]=na.w;
            Bs[nb2][lk+0][lr]=nb.x; Bs[nb2][lk+1][lr]=nb.y; Bs[nb2][lk+2][lr]=nb.z; Bs[nb2][lk+3][lr]=nb.w;
        }
        __syncthreads();
        buf ^= 1;
    }

    #pragma unroll
    for (int i = 0; i < 8; ++i) {
        float* Cp = C + (size_t)(row0 + ty*8 + i) * N + col0 + tx*8;
        *(float4*)(Cp)   = make_float4(acc[i][0], acc[i][1], acc[i][2], acc[i][3]);
        *(float4*)(Cp+4) = make_float4(acc[i][4], acc[i][5], acc[i][6], acc[i][7]);
    }
}

// ---------------------------------------------------------------------------
// alpha/beta: per token m compute sigmoid(x@Wa^T + ba) (16) and sigmoid(x@Wb^T + bb) (16)
// one block per token; x row cached in shared; each warp does 4 dot products.
// layout: g_ab[m*32 + h] = alpha_h, g_ab[m*32 + 16 + h] = beta_h
// ---------------------------------------------------------------------------
__global__ __launch_bounds__(256) void ab_kernel(const float* __restrict__ x,
                                                 const float* __restrict__ Wa,
                                                 const float* __restrict__ ba,
                                                 const float* __restrict__ Wb,
                                                 const float* __restrict__ bb,
                                                 float* __restrict__ ab)
{
    const int m   = blockIdx.x;
    const int tid = threadIdx.x;
    __shared__ float xs[HH];
    *(float4*)&xs[tid*4] = *(const float4*)&x[(size_t)m*HH + tid*4];
    __syncthreads();

    const int warp = tid >> 5, lane = tid & 31;
    for (int o = warp; o < 32; o += 8) {
        const float* w = (o < 16) ? (Wa + (size_t)o*HH) : (Wb + (size_t)(o-16)*HH);
        float sum = 0.f;
        #pragma unroll 8
        for (int kk = lane; kk < HH; kk += 32)
            sum = fmaf(xs[kk], w[kk], sum);
        #pragma unroll
        for (int off = 16; off; off >>= 1)
            sum += __shfl_xor_sync(0xffffffffu, sum, off);
        if (lane == 0) {
            float bias = (o < 16) ? ba[o] : bb[o-16];
            float y = sum + bias;
            ab[(size_t)m*32 + o] = 1.f / (1.f + expf(-y));
        }
    }
}

// ---------------------------------------------------------------------------
// activations: l2-normalize q and k per (token,head) group of 64; silu(v) in place.
// one warp per group, lane handles elems {lane, lane+32}.
// ---------------------------------------------------------------------------
__global__ __launch_bounds__(256) void act_kernel(float* __restrict__ q,
                                                  float* __restrict__ k,
                                                  float* __restrict__ v)
{
    const int g    = blockIdx.x * 8 + (threadIdx.x >> 5);
    const int lane = threadIdx.x & 31;
    const size_t base = (size_t)g * HDD;

    // q
    {
        float a0 = q[base + lane], a1 = q[base + lane + 32];
        float ss = a0*a0 + a1*a1;
        #pragma unroll
        for (int off = 16; off; off >>= 1) ss += __shfl_xor_sync(0xffffffffu, ss, off);
        float inv = 1.f / fmaxf(sqrtf(ss), 1e-12f);
        q[base + lane] = a0 * inv;  q[base + lane + 32] = a1 * inv;
    }
    // k
    {
        float a0 = k[base + lane], a1 = k[base + lane + 32];
        float ss = a0*a0 + a1*a1;
        #pragma unroll
        for (int off = 16; off; off >>= 1) ss += __shfl_xor_sync(0xffffffffu, ss, off);
        float inv = 1.f / fmaxf(sqrtf(ss), 1e-12f);
        k[base + lane] = a0 * inv;  k[base + lane + 32] = a1 * inv;
    }
    // v silu
    {
        float a0 = v[base + lane], a1 = v[base + lane + 32];
        v[base + lane]      = a0 / (1.f + expf(-a0));
        v[base + lane + 32] = a1 / (1.f + expf(-a1));
    }
}

// ---------------------------------------------------------------------------
// sequential scan over S. One block per (b,h); 256 threads: row i = tid>>2 (0..63),
// col group c = tid&3 (16 cols each). 16 state elements per thread in registers.
// Double-buffered shared staging of k/v/q/alpha/beta so global latency overlaps compute.
//   s[i][j] = a * s[i][j] * (1 - b*k_i*k_j) + b*v_i*k_j ;  out_i = sum_j s[i][j]*q_j
// ---------------------------------------------------------------------------
__global__ __launch_bounds__(256) void scan_kernel(const float* __restrict__ q,
                                                   const float* __restrict__ k,
                                                   const float* __restrict__ v,
                                                   const float* __restrict__ ab,
                                                   float* __restrict__ attn)
{
    const int bh = blockIdx.x;
    const int b  = bh >> 4;
    const int h  = bh & 15;
    const int tid = threadIdx.x;
    const int i  = tid >> 2;   // state row
    const int c  = tid & 3;    // col group

    __shared__ float sk[2][64], sv[2][64], sq[2][64], sab[2][2];

    auto base = [&](int t) { return ((size_t)(b*SS + t) * HH + h*HDD); };

    // stage step 0
    {
        size_t b0 = base(0);
        if (tid < 64)        sk[0][tid]     = k[b0 + tid];
        else if (tid < 128)  sv[0][tid-64]  = v[b0 + tid - 64];
        else if (tid < 192)  sq[0][tid-128] = q[b0 + tid - 128];
        else if (tid == 192) sab[0][0] = ab[(size_t)(b*SS + 0)*32 + h];
        else if (tid == 193) sab[0][1] = ab[(size_t)(b*SS + 0)*32 + 16 + h];
    }
    __syncthreads();

    float s[16];
    #pragma unroll
    for (int j = 0; j < 16; ++j) s[j] = 0.f;

    for (int t = 0; t < SS; ++t) {
        const int cur = t & 1;
        const bool have_next = (t + 1 < SS);
        float r = 0.f;
        if (have_next) {
            size_t nb = base(t+1);
            if (tid < 64)        r = k[nb + tid];
            else if (tid < 128)  r = v[nb + tid - 64];
            else if (tid < 192)  r = q[nb + tid - 128];
            else if (tid == 192) r = ab[(size_t)(b*SS + t + 1)*32 + h];
            else if (tid == 193) r = ab[(size_t)(b*SS + t + 1)*32 + 16 + h];
        }

        const float a  = sab[cur][0];
        const float be = sab[cur][1];
        const float ki = sk[cur][i];
        const float vi = sv[cur][i];

        float kf[16], qf[16];
        #pragma unroll
        for (int w = 0; w < 4; ++w) {
            *(float4*)&kf[w*4] = *(const float4*)&sk[cur][c*16 + w*4];
            *(float4*)&qf[w*4] = *(const float4*)&sq[cur][c*16 + w*4];
        }

        float partial = 0.f;
        #pragma unroll
        for (int j = 0; j < 16; ++j) {
            float bkj = be * kf[j];
            float u   = 1.f - ki * bkj;        // fma
            float as  = a * s[j];
            s[j]      = fmaf(as, u, vi * bkj);
            partial   = fmaf(s[j], qf[j], partial);
        }
        partial += __shfl_xor_sync(0xffffffffu, partial, 1);
        partial += __shfl_xor_sync(0xffffffffu, partial, 2);
        if (c == 0) attn[base(t) + i] = partial;

        if (have_next) {
            const int nx = cur ^ 1;
            if (tid < 64)        sk[nx][tid]     = r;
            else if (tid < 128)  sv[nx][tid-64]  = r;
            else if (tid < 192)  sq[nx][tid-128] = r;
            else if (tid == 192) sab[nx][0] = r;
            else if (tid == 193) sab[nx][1] = r;
        }
        __syncthreads();
    }
}

// ---------------------------------------------------------------------------
// layernorm over H + gate: z = LN(attn)*ln_g + ln_b, then * silu(gatebuf)
// one block per token, 256 threads x 4 elems.
// ---------------------------------------------------------------------------
__global__ __launch_bounds__(256) void ln_gate_kernel(const float* __restrict__ attn,
                                                      const float* __restrict__ gate,
                                                      const float* __restrict__ ln_g,
                                                      const float* __restrict__ ln_b,
                                                      float* __restrict__ z)
{
    const int m   = blockIdx.x;
    const int tid = threadIdx.x;
    const size_t rb = (size_t)m * HH + tid*4;

    float4 xv = *(const float4*)&attn[rb];
    float s  = xv.x + xv.y + xv.z + xv.w;
    float ss = xv.x*xv.x + xv.y*xv.y + xv.z*xv.z + xv.w*xv.w;
    #pragma unroll
    for (int off = 16; off; off >>= 1) {
        s  += __shfl_xor_sync(0xffffffffu, s,  off);
        ss += __shfl_xor_sync(0xffffffffu, ss, off);
    }
    __shared__ float rs[8], rss[8];
    if ((tid & 31) == 0) { rs[tid>>5] = s; rss[tid>>5] = ss; }
    __syncthreads();
    float tot = 0.f, tots = 0.f;
    #pragma unroll
    for (int w = 0; w < 8; ++w) { tot += rs[w]; tots += rss[w]; }

    const float mean = tot * (1.f/HH);
    const float var  = tots * (1.f/HH) - mean*mean;
    const float inv  = rsqrtf(var + 1e-5f);

    float4 gv = *(const float4*)&gate[rb];
    float4 lg = *(const float4*)&ln_g[tid*4];
    float4 lb = *(const float4*)&ln_b[tid*4];

    float4 o;
    o.x = ((xv.x-mean)*inv*lg.x + lb.x) * (gv.x / (1.f + expf(-gv.x)));
    o.y = ((xv.y-mean)*inv*lg.y + lb.y) * (gv.y / (1.f + expf(-gv.y)));
    o.z = ((xv.z-mean)*inv*lg.z + lb.z) * (gv.z / (1.f + expf(-gv.z)));
    o.w = ((xv.w-mean)*inv*lg.w + lb.w) * (gv.w / (1.f + expf(-gv.w)));
    *(float4*)&z[rb] = o;
}

// ---------------------------------------------------------------------------
extern "C" void kernel_launch(void* const* d_in, const int* in_sizes, int n_in,
                              void* d_out, int out_size)
{
    const float* x    = (const float*)d_in[0];
    const float* Wq   = (const float*)d_in[1];
    const float* Wk   = (const float*)d_in[2];
    const float* Wv   = (const float*)d_in[3];
    const float* Wa   = (const float*)d_in[4];
    const float* ba   = (const float*)d_in[5];
    const float* Wb   = (const float*)d_in[6];
    const float* bb   = (const float*)d_in[7];
    const float* Wg   = (const float*)d_in[8];
    const float* Wo   = (const float*)d_in[9];
    const float* ln_g = (const float*)d_in[10];
    const float* ln_b = (const float*)d_in[11];
    float* out = (float*)d_out;

    float *qp, *kp, *vp, *gp, *abp, *attnp, *zp;
    cudaGetSymbolAddress((void**)&qp,    g_q);
    cudaGetSymbolAddress((void**)&kp,    g_k);
    cudaGetSymbolAddress((void**)&vp,    g_v);
    cudaGetSymbolAddress((void**)&gp,    g_g);
    cudaGetSymbolAddress((void**)&abp,   g_ab);
    cudaGetSymbolAddress((void**)&attnp, g_attn);
    cudaGetSymbolAddress((void**)&zp,    g_z);

    dim3 grid_g(HH/128, MM/128);   // (8, 64)

    sgemm_nt<<<grid_g, 256>>>(x, Wq, qp, HH, HH);
    sgemm_nt<<<grid_g, 256>>>(x, Wk, kp, HH, HH);
    sgemm_nt<<<grid_g, 256>>>(x, Wv, vp, HH, HH);
    sgemm_nt<<<grid_g, 256>>>(x, Wg, gp, HH, HH);

    ab_kernel<<<MM, 256>>>(x, Wa, ba, Wb, bb, abp);
    act_kernel<<<(MM*NHH)/8, 256>>>(qp, kp, vp);

    scan_kernel<<<BB*NHH, 256>>>(qp, kp, vp, abp, attnp);

    ln_gate_kernel<<<MM, 256>>>(attnp, gp, ln_g, ln_b, zp);

    sgemm_nt<<<grid_g, 256>>>(zp, Wo, out, HH, HH);
}

// round 2
// speedup vs baseline: 1.2715x; 1.2715x over previous
#include <cuda_runtime.h>
#include <math.h>

#define BB   4
#define SS   2048
#define HH   1024
#define NHH  16
#define HDD  64
#define MM   (BB*SS)   /* 8192 tokens */

// ---------------- scratch (device globals: allocation-free) ----------------
__device__ float g_q[(size_t)MM*HH];
__device__ float g_k[(size_t)MM*HH];
__device__ float g_v[(size_t)MM*HH];
__device__ float g_g[(size_t)MM*HH];
__device__ float g_ab[(size_t)MM*2*NHH];
__device__ float g_attn[(size_t)MM*HH];
__device__ float g_z[(size_t)MM*HH];

// ---------------------------------------------------------------------------
// packed f32x2 helpers (sm_100+ PTX; ptxas never auto-generates these)
// ---------------------------------------------------------------------------
typedef unsigned long long ull;
__device__ __forceinline__ ull pk2(float x, float y) {
    ull r; asm("mov.b64 %0, {%1,%2};" : "=l"(r) : "f"(x), "f"(y)); return r;
}
__device__ __forceinline__ ull mul2(ull a, ull b) {
    ull d; asm("mul.rn.f32x2 %0, %1, %2;" : "=l"(d) : "l"(a), "l"(b)); return d;
}
__device__ __forceinline__ ull add2(ull a, ull b) {
    ull d; asm("add.rn.f32x2 %0, %1, %2;" : "=l"(d) : "l"(a), "l"(b)); return d;
}
__device__ __forceinline__ ull fma2(ull a, ull b, ull c) {
    ull d; asm("fma.rn.f32x2 %0, %1, %2, %3;" : "=l"(d) : "l"(a), "l"(b), "l"(c)); return d;
}
__device__ __forceinline__ float2 upk2(ull a) {
    float2 f; asm("mov.b64 {%0,%1}, %2;" : "=f"(f.x), "=f"(f.y) : "l"(a)); return f;
}

__device__ __forceinline__ void cp_async16(void* dst_smem, const void* src_gmem) {
    unsigned dst = (unsigned)__cvta_generic_to_shared(dst_smem);
    asm volatile("cp.async.cg.shared.global [%0], [%1], 16;\n" :: "r"(dst), "l"(src_gmem));
}
__device__ __forceinline__ void cp_async_commit() {
    asm volatile("cp.async.commit_group;\n");
}
__device__ __forceinline__ void cp_async_wait0() {
    asm volatile("cp.async.wait_group 0;\n");
}

// ---------------------------------------------------------------------------
// SGEMM: C[M,N] = A[M,K] @ B[N,K]^T  (both row-major), tiles 128x128x8,
// 256 threads, 8x8 per thread, double-buffered shared.  (unchanged from R1)
// ---------------------------------------------------------------------------
__global__ __launch_bounds__(256) void sgemm_nt(const float* __restrict__ A,
                                                const float* __restrict__ Bm,
                                                float* __restrict__ C,
                                                int K, int N)
{
    const int tid  = threadIdx.x;
    const int tx   = tid & 15;
    const int ty   = tid >> 4;
    const int row0 = blockIdx.y * 128;
    const int col0 = blockIdx.x * 128;

    __shared__ float As[2][8][128];
    __shared__ float Bs[2][8][128];

    const int lr = tid >> 1;
    const int lk = (tid & 1) << 2;
    const float* Ap = A  + (size_t)(row0 + lr) * K + lk;
    const float* Bp = Bm + (size_t)(col0 + lr) * K + lk;

    float4 a4 = *(const float4*)Ap;
    float4 b4 = *(const float4*)Bp;
    As[0][lk+0][lr]=a4.x; As[0][lk+1][lr]=a4.y; As[0][lk+2][lr]=a4.z; As[0][lk+3][lr]=a4.w;
    Bs[0][lk+0][lr]=b4.x; Bs[0][lk+1][lr]=b4.y; Bs[0][lk+2][lr]=b4.z; Bs[0][lk+3][lr]=b4.w;
    __syncthreads();

    float acc[8][8] = {};
    const int nk = K >> 3;
    int buf = 0;

    for (int kt = 0; kt < nk; ++kt) {
        float4 na, nb;
        const bool have_next = (kt + 1 < nk);
        if (have_next) {
            na = *(const float4*)(Ap + (size_t)(kt+1)*8);
            nb = *(const float4*)(Bp + (size_t)(kt+1)*8);
        }
        #pragma unroll
        for (int kk = 0; kk < 8; ++kk) {
            float af[8], bf[8];
            *(float4*)(af)   = *(const float4*)&As[buf][kk][ty*8];
            *(float4*)(af+4) = *(const float4*)&As[buf][kk][ty*8+4];
            *(float4*)(bf)   = *(const float4*)&Bs[buf][kk][tx*8];
            *(float4*)(bf+4) = *(const float4*)&Bs[buf][kk][tx*8+4];
            #pragma unroll
            for (int i = 0; i < 8; ++i)
                #pragma unroll
                for (int j = 0; j < 8; ++j)
                    acc[i][j] = fmaf(af[i], bf[j], acc[i][j]);
        }
        if (have_next) {
            const int nb2 = buf ^ 1;
            As[nb2][lk+0][lr]=na.x; As[nb2][lk+1][lr]=na.y; As[nb2][lk+2][lr]=na.z; As[nb2][lk+3][lr]=na.w;
            Bs[nb2][lk+0][lr]=nb.x; Bs[nb2][lk+1][lr]=nb.y; Bs[nb2][lk+2][lr]=nb.z; Bs[nb2][lk+3][lr]=nb.w;
        }
        __syncthreads();
        buf ^= 1;
    }

    #pragma unroll
    for (int i = 0; i < 8; ++i) {
        float* Cp = C + (size_t)(row0 + ty*8 + i) * N + col0 + tx*8;
        *(float4*)(Cp)   = make_float4(acc[i][0], acc[i][1], acc[i][2], acc[i][3]);
        *(float4*)(Cp+4) = make_float4(acc[i][4], acc[i][5], acc[i][6], acc[i][7]);
    }
}

// ---------------------------------------------------------------------------
// alpha/beta: 8 tokens per block, weight rows register-resident per warp.
// layout: g_ab[m*32 + o] = sigmoid(x_m @ W_o + b_o), o<16 -> alpha, o>=16 -> beta
// ---------------------------------------------------------------------------
__global__ __launch_bounds__(256) void ab_kernel(const float* __restrict__ x,
                                                 const float* __restrict__ Wa,
                                                 const float* __restrict__ ba,
                                                 const float* __restrict__ Wb,
                                                 const float* __restrict__ bb,
                                                 float* __restrict__ ab)
{
    const int m0  = blockIdx.x * 8;
    const int tid = threadIdx.x;
    __shared__ float xs[8][HH];

    // load 8 token rows (2048 float4 / 256 threads = 8 each), coalesced
    for (int n = tid; n < 8 * HH / 4; n += 256) {
        const int tok = n / (HH/4);
        const int e4  = (n % (HH/4)) * 4;
        *(float4*)&xs[tok][e4] = *(const float4*)&x[(size_t)(m0 + tok)*HH + e4];
    }
    __syncthreads();

    const int warp = tid >> 5, lane = tid & 31;
    for (int o = warp; o < 32; o += 8) {
        const float* w = (o < 16) ? (Wa + (size_t)o*HH) : (Wb + (size_t)(o-16)*HH);
        float wr[32];
        #pragma unroll
        for (int u = 0; u < 32; ++u) wr[u] = w[lane + u*32];
        const float bias = (o < 16) ? ba[o] : bb[o-16];
        for (int tok = 0; tok < 8; ++tok) {
            float sum = 0.f;
            #pragma unroll
            for (int u = 0; u < 32; ++u)
                sum = fmaf(wr[u], xs[tok][lane + u*32], sum);
            #pragma unroll
            for (int off = 16; off; off >>= 1)
                sum += __shfl_xor_sync(0xffffffffu, sum, off);
            if (lane == 0) {
                float y = sum + bias;
                ab[(size_t)(m0 + tok)*32 + o] = 1.f / (1.f + expf(-y));
            }
        }
    }
}

// ---------------------------------------------------------------------------
// activations: l2-normalize q and k per (token,head); silu(v) in place.
// ---------------------------------------------------------------------------
__global__ __launch_bounds__(256) void act_kernel(float* __restrict__ q,
                                                  float* __restrict__ k,
                                                  float* __restrict__ v)
{
    const int g    = blockIdx.x * 8 + (threadIdx.x >> 5);
    const int lane = threadIdx.x & 31;
    const size_t base = (size_t)g * HDD;

    {
        float a0 = q[base + lane], a1 = q[base + lane + 32];
        float ss = a0*a0 + a1*a1;
        #pragma unroll
        for (int off = 16; off; off >>= 1) ss += __shfl_xor_sync(0xffffffffu, ss, off);
        float inv = 1.f / fmaxf(sqrtf(ss), 1e-12f);
        q[base + lane] = a0 * inv;  q[base + lane + 32] = a1 * inv;
    }
    {
        float a0 = k[base + lane], a1 = k[base + lane + 32];
        float ss = a0*a0 + a1*a1;
        #pragma unroll
        for (int off = 16; off; off >>= 1) ss += __shfl_xor_sync(0xffffffffu, ss, off);
        float inv = 1.f / fmaxf(sqrtf(ss), 1e-12f);
        k[base + lane] = a0 * inv;  k[base + lane + 32] = a1 * inv;
    }
    {
        float a0 = v[base + lane], a1 = v[base + lane + 32];
        v[base + lane]      = a0 / (1.f + expf(-a0));
        v[base + lane + 32] = a1 / (1.f + expf(-a1));
    }
}

// ---------------------------------------------------------------------------
// Sequential scan, tile-staged. One block per (b,h); 256 threads:
// row i = tid>>2 (0..63), col group c = tid&3 (16 cols -> 8 f32x2 lanes each).
// Per step (all from shared, no syncs):
//   w_j = beta*k_j ; r = alpha*s ; s' = r + w_j*(v_i - k_i*r) ; out += s'*q_j
// k/v/q staged TILE steps at a time via cp.async (double buffered);
// alpha/beta for all SS steps staged once at start.
// ---------------------------------------------------------------------------
#define TILE 16
#define NTILE (SS/TILE)

__global__ __launch_bounds__(256) void scan_kernel(const float* __restrict__ q,
                                                   const float* __restrict__ k,
                                                   const float* __restrict__ v,
                                                   const float* __restrict__ ab,
                                                   float* __restrict__ attn)
{
    const int bh  = blockIdx.x;
    const int b   = bh >> 4;
    const int h   = bh & 15;
    const int tid = threadIdx.x;
    const int i   = tid >> 2;   // state row 0..63
    const int c   = tid & 3;    // col group 0..3

    __shared__ float sk[2][TILE][64];
    __shared__ float sv[2][TILE][64];
    __shared__ float sq[2][TILE][64];
    __shared__ float sab[SS][2];          // 16 KB, loaded once

    auto base = [&](int t) { return ((size_t)(b*SS + t) * HH + (size_t)h*HDD); };

    // ---- stage tile 0 (async) ----
    {
        const int tt = tid >> 4;          // 0..15
        const int e4 = (tid & 15) << 2;   // 0,4,...,60
        cp_async16(&sk[0][tt][e4], k + base(tt) + e4);
        cp_async16(&sv[0][tt][e4], v + base(tt) + e4);
        cp_async16(&sq[0][tt][e4], q + base(tt) + e4);
        cp_async_commit();
    }
    // ---- stage all alpha/beta (plain loads, overlaps the cp.async) ----
    for (int t = tid; t < SS; t += 256) {
        const size_t o = (size_t)(b*SS + t) * 32;
        sab[t][0] = ab[o + h];
        sab[t][1] = ab[o + 16 + h];
    }
    cp_async_wait0();
    __syncthreads();

    // state: 16 elems as 8 packed f32x2
    ull s2[8];
    #pragma unroll
    for (int j = 0; j < 8; ++j) s2[j] = 0ull;

    int buf = 0;
    for (int tile = 0; tile < NTILE; ++tile) {
        const int t0 = tile * TILE;
        // prefetch next tile into buf^1 (fire and forget)
        if (tile + 1 < NTILE) {
            const int nx = buf ^ 1;
            const int tt = tid >> 4;
            const int e4 = (tid & 15) << 2;
            const size_t nb = base(t0 + TILE + tt) + e4;
            cp_async16(&sk[nx][tt][e4], k + nb);
            cp_async16(&sv[nx][tt][e4], v + nb);
            cp_async16(&sq[nx][tt][e4], q + nb);
            cp_async_commit();
        }

        #pragma unroll 4
        for (int tt = 0; tt < TILE; ++tt) {
            const int t = t0 + tt;
            const float2 abv = *(const float2*)&sab[t][0];
            const float a  = abv.x;
            const float be = abv.y;
            const float ki = sk[buf][tt][i];
            const float vi = sv[buf][tt][i];

            const ull a2   = pk2(a, a);
            const ull be2  = pk2(be, be);
            const ull vi2  = pk2(vi, vi);
            const ull nki2 = pk2(-ki, -ki);

            ull k2[8], q2[8];
            {
                const ulonglong2* kp = (const ulonglong2*)&sk[buf][tt][c*16];
                const ulonglong2* qp = (const ulonglong2*)&sq[buf][tt][c*16];
                #pragma unroll
                for (int w = 0; w < 4; ++w) {
                    ulonglong2 kk = kp[w]; k2[w*2] = kk.x; k2[w*2+1] = kk.y;
                    ulonglong2 qq = qp[w]; q2[w*2] = qq.x; q2[w*2+1] = qq.y;
                }
            }

            ull pa = 0ull, pb = 0ull;
            #pragma unroll
            for (int j = 0; j < 8; ++j) {
                const ull w2  = mul2(be2, k2[j]);
                const ull r   = mul2(a2, s2[j]);
                const ull tmp = fma2(nki2, r, vi2);   // v_i - k_i * r
                s2[j] = fma2(w2, tmp, r);
                if (j & 1) pb = fma2(s2[j], q2[j], pb);
                else       pa = fma2(s2[j], q2[j], pa);
            }
            const float2 ps = upk2(add2(pa, pb));
            float partial = ps.x + ps.y;
            partial += __shfl_xor_sync(0xffffffffu, partial, 1);
            partial += __shfl_xor_sync(0xffffffffu, partial, 2);
            if (c == 0) attn[base(t) + i] = partial;
        }

        if (tile + 1 < NTILE) cp_async_wait0();
        __syncthreads();
        buf ^= 1;
    }
}

// ---------------------------------------------------------------------------
// layernorm over H + gate
// ---------------------------------------------------------------------------
__global__ __launch_bounds__(256) void ln_gate_kernel(const float* __restrict__ attn,
                                                      const float* __restrict__ gate,
                                                      const float* __restrict__ ln_g,
                                                      const float* __restrict__ ln_b,
                                                      float* __restrict__ z)
{
    const int m   = blockIdx.x;
    const int tid = threadIdx.x;
    const size_t rb = (size_t)m * HH + tid*4;

    float4 xv = *(const float4*)&attn[rb];
    float s  = xv.x + xv.y + xv.z + xv.w;
    float ss = xv.x*xv.x + xv.y*xv.y + xv.z*xv.z + xv.w*xv.w;
    #pragma unroll
    for (int off = 16; off; off >>= 1) {
        s  += __shfl_xor_sync(0xffffffffu, s,  off);
        ss += __shfl_xor_sync(0xffffffffu, ss, off);
    }
    __shared__ float rs[8], rss[8];
    if ((tid & 31) == 0) { rs[tid>>5] = s; rss[tid>>5] = ss; }
    __syncthreads();
    float tot = 0.f, tots = 0.f;
    #pragma unroll
    for (int w = 0; w < 8; ++w) { tot += rs[w]; tots += rss[w]; }

    const float mean = tot * (1.f/HH);
    const float var  = tots * (1.f/HH) - mean*mean;
    const float inv  = rsqrtf(var + 1e-5f);

    float4 gv = *(const float4*)&gate[rb];
    float4 lg = *(const float4*)&ln_g[tid*4];
    float4 lb = *(const float4*)&ln_b[tid*4];

    float4 o;
    o.x = ((xv.x-mean)*inv*lg.x + lb.x) * (gv.x / (1.f + expf(-gv.x)));
    o.y = ((xv.y-mean)*inv*lg.y + lb.y) * (gv.y / (1.f + expf(-gv.y)));
    o.z = ((xv.z-mean)*inv*lg.z + lb.z) * (gv.z / (1.f + expf(-gv.z)));
    o.w = ((xv.w-mean)*inv*lg.w + lb.w) * (gv.w / (1.f + expf(-gv.w)));
    *(float4*)&z[rb] = o;
}

// ---------------------------------------------------------------------------
extern "C" void kernel_launch(void* const* d_in, const int* in_sizes, int n_in,
                              void* d_out, int out_size)
{
    const float* x    = (const float*)d_in[0];
    const float* Wq   = (const float*)d_in[1];
    const float* Wk   = (const float*)d_in[2];
    const float* Wv   = (const float*)d_in[3];
    const float* Wa   = (const float*)d_in[4];
    const float* ba   = (const float*)d_in[5];
    const float* Wb   = (const float*)d_in[6];
    const float* bb   = (const float*)d_in[7];
    const float* Wg   = (const float*)d_in[8];
    const float* Wo   = (const float*)d_in[9];
    const float* ln_g = (const float*)d_in[10];
    const float* ln_b = (const float*)d_in[11];
    float* out = (float*)d_out;

    float *qp, *kp, *vp, *gp, *abp, *attnp, *zp;
    cudaGetSymbolAddress((void**)&qp,    g_q);
    cudaGetSymbolAddress((void**)&kp,    g_k);
    cudaGetSymbolAddress((void**)&vp,    g_v);
    cudaGetSymbolAddress((void**)&gp,    g_g);
    cudaGetSymbolAddress((void**)&abp,   g_ab);
    cudaGetSymbolAddress((void**)&attnp, g_attn);
    cudaGetSymbolAddress((void**)&zp,    g_z);

    dim3 grid_g(HH/128, MM/128);   // (8, 64)

    sgemm_nt<<<grid_g, 256>>>(x, Wq, qp, HH, HH);
    sgemm_nt<<<grid_g, 256>>>(x, Wk, kp, HH, HH);
    sgemm_nt<<<grid_g, 256>>>(x, Wv, vp, HH, HH);
    sgemm_nt<<<grid_g, 256>>>(x, Wg, gp, HH, HH);

    ab_kernel<<<MM/8, 256>>>(x, Wa, ba, Wb, bb, abp);
    act_kernel<<<(MM*NHH)/8, 256>>>(qp, kp, vp);

    scan_kernel<<<BB*NHH, 256>>>(qp, kp, vp, abp, attnp);

    ln_gate_kernel<<<MM, 256>>>(attnp, gp, ln_g, ln_b, zp);

    sgemm_nt<<<grid_g, 256>>>(zp, Wo, out, HH, HH);
}